// round 14
// baseline (speedup 1.0000x reference)
#include <cuda_runtime.h>
#include <cuda_fp16.h>
#include <cstdint>
#include <cstddef>

// ============================================================================
//   out[t,m] = sum_j xr[t,j] * Wcat[m,j],  xr = [x@Pi1^T | x@Pi2^T]  (K = 8192)
//   xr[t,j]  = sum_k x[t,k]  * Pcat[j,k]   (Pcat = [Pi1; Pi2], N = 8192, K = 4096)
// ============================================================================
#define TOK    512
#define NF     4096
#define KSTEP  64                          // halves of K per stage (128 B rows)
#define NSTG   3
#define TT     128
#define TJ     128
#define STAGE_ROWS (TT + TJ)               // 256
#define STAGE_BYTES (STAGE_ROWS * 128)     // 32768
#define SMEM_BYTES  (NSTG * STAGE_BYTES)   // 98304 -> 2 CTAs/SM
#define AUX_Y   10                         // 40 aux CTAs inside GEMM1 launch
#define SK_CTAS 296                        // stream-K grid for GEMM2

// ============================================================================
// Device scratch (no cudaMalloc allowed)
// ============================================================================
static __device__ __half g_x16[(size_t)TOK * NF];          //  4 MB
static __device__ __half g_P16[(size_t)2 * NF * NF];       // 64 MB  [Pi1; Pi2]
static __device__ __half g_W16[(size_t)NF * 2 * NF];       // 64 MB  [W1 | W2] per row
static __device__ __half g_xr [(size_t)TOK * 2 * NF];      //  8 MB  [xr1 | xr2]

static __device__ __forceinline__ uint32_t smem_u32(const void* p) {
    uint32_t a;
    asm("{ .reg .u64 t; cvta.to.shared.u64 t, %1; cvt.u32.u64 %0, t; }"
        : "=r"(a) : "l"(p));
    return a;
}

#define TQ_LDSM4(r0, r1, r2, r3, addr) \
    asm volatile("ldmatrix.sync.aligned.m8n8.x4.shared.b16 {%0,%1,%2,%3}, [%4];" \
                 : "=r"(r0), "=r"(r1), "=r"(r2), "=r"(r3) : "r"(addr))

// ============================================================================
// Prep kernel A: Pi + Pi2 fp32 -> fp16 (192 MB traffic, DRAM-cap bound)
// ============================================================================
__global__ void tq_prep_p(const float4* __restrict__ Pi, const float4* __restrict__ Pi2,
                          __half2* __restrict__ P16) {
    const int n4 = NF * NF / 4;
    int i = blockIdx.x * 1024 + threadIdx.x;
    #pragma unroll
    for (int j = 0; j < 4; ++j) {
        int k = i + j * 256;
        float4 v = (k < n4) ? Pi[k] : Pi2[k - n4];
        P16[2 * k]     = __floats2half2_rn(v.x, v.y);
        P16[2 * k + 1] = __floats2half2_rn(v.z, v.w);
    }
}

// ============================================================================
// Prep kernel B (block-range dispatch, 5120 blocks):
//   [0, 512)      : x fp32 -> fp16
//   [512, 4608)   : dequant pass 2 -> g_W16[:, NF:]
//   [4608, 5120)  : zero fp32 output (atomicAdd target of GEMM2)
// ============================================================================
__global__ void tq_prep_rest(const float4* __restrict__ x, __half2* __restrict__ x16,
                             const int4* __restrict__ IP4, const float* __restrict__ NRM,
                             const float* __restrict__ CB, __half* __restrict__ W16,
                             float4* __restrict__ zo)
{
    const int b = blockIdx.x;
    if (b < 512) {                        // --- x conversion (10 MB)
        int i = b * 1024 + threadIdx.x;
        #pragma unroll
        for (int j = 0; j < 4; ++j) {
            int k = i + j * 256;
            float4 v = x[k];
            x16[2 * k]     = __floats2half2_rn(v.x, v.y);
            x16[2 * k + 1] = __floats2half2_rn(v.z, v.w);
        }
    } else if (b < 4608) {                // --- dequant pass 2 (64 MB)
        __shared__ float cb[16];
        if (threadIdx.x < 16) cb[threadIdx.x] = CB[threadIdx.x];
        __syncthreads();
        int base = (b - 512) * 512 + threadIdx.x;
        #pragma unroll
        for (int u = 0; u < 2; ++u) {
            int i = base + u * 256;
            int m  = i >> 9;
            int c4 = i & 511;
            int4 p = IP4[i];
            float s = __ldg(&NRM[(m << 5) + (c4 >> 4)]) * 0.08838834764831843f;
            __half2 h[4];
            h[0] = __floats2half2_rn(cb[p.x & 15] * s, cb[(p.x >> 4) & 15] * s);
            h[1] = __floats2half2_rn(cb[p.y & 15] * s, cb[(p.y >> 4) & 15] * s);
            h[2] = __floats2half2_rn(cb[p.z & 15] * s, cb[(p.z >> 4) & 15] * s);
            h[3] = __floats2half2_rn(cb[p.w & 15] * s, cb[(p.w >> 4) & 15] * s);
            *reinterpret_cast<uint4*>(W16 + (size_t)m * (2 * NF) + NF + c4 * 8) =
                *reinterpret_cast<uint4*>(h);
        }
    } else {                              // --- zero out (8 MB)
        int i = (b - 4608) * 1024 + threadIdx.x;
        #pragma unroll
        for (int j = 0; j < 4; ++j)
            zo[i + j * 256] = make_float4(0.f, 0.f, 0.f, 0.f);
    }
}

// ============================================================================
// GEMM1 + aux (r12/r13 exact): tile 128x128, 8 warps, warp 64x32,
//   3-stage cp.async, fragment double-buffered; aux CTAs run dq pass 1.
// ============================================================================
__global__ void __launch_bounds__(256, 2)
tq_hgemm_aux(const __half* __restrict__ X, int ldx,
             const __half* __restrict__ W, int ldw,
             int ksteps, int jTiles, __half* __restrict__ Ch, int ldc,
             const int4* __restrict__ dq_i1, const float* __restrict__ dq_n1,
             const float* __restrict__ dq_c1, __half* __restrict__ dq_out)
{
    extern __shared__ __align__(1024) char dsm[];

    // ---------------- aux path: dq1 (64 MB over 40 CTAs) --------------------
    if ((int)blockIdx.y >= jTiles) {
        float* cb = reinterpret_cast<float*>(dsm);
        if (threadIdx.x < 16) cb[threadIdx.x] = dq_c1[threadIdx.x];
        __syncthreads();
        const int auxId  = (blockIdx.y - jTiles) * gridDim.x + blockIdx.x;
        const int nAux   = AUX_Y * gridDim.x;
        const int total   = NF * (NF / 2) / 4;
        const int start4  = (auxId * 256 + threadIdx.x) * 4;
        const int stride4 = nAux * 256 * 4;
        for (int i0 = start4; i0 < total; i0 += stride4) {
            int4 p[4];
            #pragma unroll
            for (int u = 0; u < 4; ++u) p[u] = dq_i1[i0 + u];
            #pragma unroll
            for (int u = 0; u < 4; ++u) {
                int i  = i0 + u;
                int m  = i >> 9;
                int c4 = i & 511;
                float s = __ldg(&dq_n1[(m << 5) + (c4 >> 4)]) * 0.08838834764831843f;
                __half2 h[4];
                h[0] = __floats2half2_rn(cb[p[u].x & 15] * s, cb[(p[u].x >> 4) & 15] * s);
                h[1] = __floats2half2_rn(cb[p[u].y & 15] * s, cb[(p[u].y >> 4) & 15] * s);
                h[2] = __floats2half2_rn(cb[p[u].z & 15] * s, cb[(p[u].z >> 4) & 15] * s);
                h[3] = __floats2half2_rn(cb[p[u].w & 15] * s, cb[(p[u].w >> 4) & 15] * s);
                *reinterpret_cast<uint4*>(dq_out + (size_t)m * (2 * NF) + c4 * 8) =
                    *reinterpret_cast<uint4*>(h);
            }
        }
        return;
    }

    // ---------------- GEMM path --------------------------------------------
    const uint32_t smBase = smem_u32(dsm);
    const int tid = threadIdx.x;
    const int wid = tid >> 5;
    const int lid = tid & 31;
    const int wm  = wid >> 2;
    const int wn  = wid & 3;
    const int tBase = blockIdx.x * TT;
    const int jBase = blockIdx.y * TJ;

    const __half* xb = X + (size_t)tBase * ldx;
    const __half* wb = W + (size_t)jBase * ldw;

    auto load_stage = [&](int slot, int step) {
        const int k0 = step * KSTEP;
        #pragma unroll
        for (int s = 0; s < 8; ++s) {
            int q = tid + s * 256;
            int r = q >> 3;
            int c = q & 7;
            const __half* src = (r < TT ? xb + (size_t)r * ldx
                                        : wb + (size_t)(r - TT) * ldw) + k0 + c * 8;
            uint32_t dst = smBase + slot * STAGE_BYTES + r * 128 + ((c ^ (r & 7)) * 16);
            asm volatile("cp.async.cg.shared.global [%0], [%1], 16;"
                         :: "r"(dst), "l"(src));
        }
    };

    const int swz  = lid & 7;
    const int rowA = wm * 64 + (lid & 7) + ((lid >> 3) & 1) * 8;
    const int pA   = lid >> 4;
    const int rowB = TT + wn * 32 + (lid & 7) + ((lid >> 4) & 1) * 8;
    const int pB   = (lid >> 3) & 1;

    float acc[4][4][4];
    #pragma unroll
    for (int a = 0; a < 4; ++a)
        #pragma unroll
        for (int b = 0; b < 4; ++b)
            #pragma unroll
            for (int c = 0; c < 4; ++c) acc[a][b][c] = 0.f;

    load_stage(0, 0);
    asm volatile("cp.async.commit_group;" ::: "memory");
    load_stage(1, 1);
    asm volatile("cp.async.commit_group;" ::: "memory");

    uint32_t a[2][4][4];
    uint32_t b[2][4][2];

    auto ldfrag = [&](int buf, uint32_t sb, int kb) {
        #pragma unroll
        for (int mi = 0; mi < 4; ++mi) {
            uint32_t ad = sb + (uint32_t)(rowA + mi * 16) * 128
                        + (uint32_t)(((kb * 2 + pA) ^ swz) * 16);
            TQ_LDSM4(a[buf][mi][0], a[buf][mi][1], a[buf][mi][2], a[buf][mi][3], ad);
        }
        #pragma unroll
        for (int gi = 0; gi < 2; ++gi) {
            uint32_t bd = sb + (uint32_t)(rowB + gi * 16) * 128
                        + (uint32_t)(((kb * 2 + pB) ^ swz) * 16);
            TQ_LDSM4(b[buf][2 * gi][0], b[buf][2 * gi][1],
                     b[buf][2 * gi + 1][0], b[buf][2 * gi + 1][1], bd);
        }
    };

    auto domma = [&](int buf) {
        #pragma unroll
        for (int mi = 0; mi < 4; ++mi)
            #pragma unroll
            for (int ni = 0; ni < 4; ++ni) {
                asm volatile(
                    "mma.sync.aligned.m16n8k16.row.col.f32.f16.f16.f32 "
                    "{%0,%1,%2,%3}, {%4,%5,%6,%7}, {%8,%9}, {%0,%1,%2,%3};"
                    : "+f"(acc[mi][ni][0]), "+f"(acc[mi][ni][1]),
                      "+f"(acc[mi][ni][2]), "+f"(acc[mi][ni][3])
                    : "r"(a[buf][mi][0]), "r"(a[buf][mi][1]),
                      "r"(a[buf][mi][2]), "r"(a[buf][mi][3]),
                      "r"(b[buf][ni][0]), "r"(b[buf][ni][1]));
            }
    };

    int slot = 0, pfslot = 2;
    for (int it = 0; it < ksteps; ++it) {
        asm volatile("cp.async.wait_group 1;" ::: "memory");
        __syncthreads();

        const int pf = it + NSTG - 1;
        if (pf < ksteps) load_stage(pfslot, pf);
        asm volatile("cp.async.commit_group;" ::: "memory");

        const uint32_t sb = smBase + slot * STAGE_BYTES;
        if (++slot == NSTG) slot = 0;
        if (++pfslot == NSTG) pfslot = 0;

        ldfrag(0, sb, 0);
        #pragma unroll
        for (int kb = 0; kb < 4; ++kb) {
            const int cur = kb & 1;
            if (kb < 3) ldfrag(cur ^ 1, sb, kb + 1);
            domma(cur);
        }
    }

    const int g  = lid >> 2;
    const int tg = lid & 3;
    #pragma unroll
    for (int mi = 0; mi < 4; ++mi) {
        #pragma unroll
        for (int ni = 0; ni < 4; ++ni) {
            int row = tBase + wm * 64 + mi * 16 + g;
            int col = jBase + wn * 32 + ni * 8 + tg * 2;
            __half2 h0 = __floats2half2_rn(acc[mi][ni][0], acc[mi][ni][1]);
            __half2 h1 = __floats2half2_rn(acc[mi][ni][2], acc[mi][ni][3]);
            *reinterpret_cast<__half2*>(Ch + (size_t)row * ldc + col)       = h0;
            *reinterpret_cast<__half2*>(Ch + (size_t)(row + 8) * ldc + col) = h1;
        }
    }
}

// ============================================================================
// GEMM2, stream-K over SK_CTAS CTAs.
//   Work unit = one K-step (64 halves) of one 128x128 output tile.
//   128 tiles x 128 ksteps = 16384 units striped contiguously over the grid.
//   Each contiguous same-tile segment: r12-exact mainloop + atomicAdd epilogue.
// ============================================================================
__global__ void __launch_bounds__(256, 2)
tq_hgemm2_sk(const __half* __restrict__ X, int ldx,
             const __half* __restrict__ W, int ldw,
             float* __restrict__ Cf, int ldc)
{
    extern __shared__ __align__(1024) char dsm[];
    const uint32_t smBase = smem_u32(dsm);

    const int tid = threadIdx.x;
    const int wid = tid >> 5;
    const int lid = tid & 31;
    const int wm  = wid >> 2;
    const int wn  = wid & 3;

    const int U = 128 * 128;                 // total work units
    const int G = gridDim.x;
    int w  = (int)(((long long)blockIdx.x * U) / G);
    const int w1 = (int)(((long long)(blockIdx.x + 1) * U) / G);

    const int swz  = lid & 7;
    const int rowA = wm * 64 + (lid & 7) + ((lid >> 3) & 1) * 8;
    const int pA   = lid >> 4;
    const int rowB = TT + wn * 32 + (lid & 7) + ((lid >> 4) & 1) * 8;
    const int pB   = (lid >> 3) & 1;
    const int g    = lid >> 2;
    const int tg   = lid & 3;

    while (w < w1) {
        const int tl   = w >> 7;             // tile index [0,128)
        const int ks0  = w & 127;            // first K-step within tile
        const int kcnt = min(128 - ks0, w1 - w);
        w += kcnt;

        const int tBase = (tl & 3) * TT;
        const int jBase = (tl >> 2) * TJ;
        const __half* xb = X + (size_t)tBase * ldx + ks0 * KSTEP;
        const __half* wb = W + (size_t)jBase * ldw + ks0 * KSTEP;

        // drain previous segment's async groups; protect smem reuse
        asm volatile("cp.async.wait_group 0;" ::: "memory");
        __syncthreads();

        auto load_stage = [&](int slot, int step) {   // step is segment-relative
            const int k0 = step * KSTEP;
            #pragma unroll
            for (int s = 0; s < 8; ++s) {
                int q = tid + s * 256;
                int r = q >> 3;
                int c = q & 7;
                const __half* src = (r < TT ? xb + (size_t)r * ldx
                                            : wb + (size_t)(r - TT) * ldw) + k0 + c * 8;
                uint32_t dst = smBase + slot * STAGE_BYTES + r * 128 + ((c ^ (r & 7)) * 16);
                asm volatile("cp.async.cg.shared.global [%0], [%1], 16;"
                             :: "r"(dst), "l"(src));
            }
        };

        float acc[4][4][4];
        #pragma unroll
        for (int ia = 0; ia < 4; ++ia)
            #pragma unroll
            for (int ib = 0; ib < 4; ++ib)
                #pragma unroll
                for (int ic = 0; ic < 4; ++ic) acc[ia][ib][ic] = 0.f;

        load_stage(0, 0);
        asm volatile("cp.async.commit_group;" ::: "memory");
        if (kcnt > 1) load_stage(1, 1);
        asm volatile("cp.async.commit_group;" ::: "memory");

        uint32_t a[2][4][4];
        uint32_t b[2][4][2];

        auto ldfrag = [&](int buf, uint32_t sb, int kb) {
            #pragma unroll
            for (int mi = 0; mi < 4; ++mi) {
                uint32_t ad = sb + (uint32_t)(rowA + mi * 16) * 128
                            + (uint32_t)(((kb * 2 + pA) ^ swz) * 16);
                TQ_LDSM4(a[buf][mi][0], a[buf][mi][1], a[buf][mi][2], a[buf][mi][3], ad);
            }
            #pragma unroll
            for (int gi = 0; gi < 2; ++gi) {
                uint32_t bd = sb + (uint32_t)(rowB + gi * 16) * 128
                            + (uint32_t)(((kb * 2 + pB) ^ swz) * 16);
                TQ_LDSM4(b[buf][2 * gi][0], b[buf][2 * gi][1],
                         b[buf][2 * gi + 1][0], b[buf][2 * gi + 1][1], bd);
            }
        };

        auto domma = [&](int buf) {
            #pragma unroll
            for (int mi = 0; mi < 4; ++mi)
                #pragma unroll
                for (int ni = 0; ni < 4; ++ni) {
                    asm volatile(
                        "mma.sync.aligned.m16n8k16.row.col.f32.f16.f16.f32 "
                        "{%0,%1,%2,%3}, {%4,%5,%6,%7}, {%8,%9}, {%0,%1,%2,%3};"
                        : "+f"(acc[mi][ni][0]), "+f"(acc[mi][ni][1]),
                          "+f"(acc[mi][ni][2]), "+f"(acc[mi][ni][3])
                        : "r"(a[buf][mi][0]), "r"(a[buf][mi][1]),
                          "r"(a[buf][mi][2]), "r"(a[buf][mi][3]),
                          "r"(b[buf][ni][0]), "r"(b[buf][ni][1]));
                }
        };

        for (int it = 0; it < kcnt; ++it) {
            asm volatile("cp.async.wait_group 1;" ::: "memory");
            __syncthreads();

            const int pf = it + 2;
            if (pf < kcnt) load_stage(pf % 3, pf);
            asm volatile("cp.async.commit_group;" ::: "memory");

            const uint32_t sb = smBase + (it % 3) * STAGE_BYTES;

            ldfrag(0, sb, 0);
            #pragma unroll
            for (int kb = 0; kb < 4; ++kb) {
                const int cur = kb & 1;
                if (kb < 3) ldfrag(cur ^ 1, sb, kb + 1);
                domma(cur);
            }
        }

        // segment epilogue: accumulate partial into fp32 output
        #pragma unroll
        for (int mi = 0; mi < 4; ++mi) {
            #pragma unroll
            for (int ni = 0; ni < 4; ++ni) {
                int row = tBase + wm * 64 + mi * 16 + g;
                int col = jBase + wn * 32 + ni * 8 + tg * 2;
                atomicAdd(Cf + (size_t)row * ldc + col,           acc[mi][ni][0]);
                atomicAdd(Cf + (size_t)row * ldc + col + 1,       acc[mi][ni][1]);
                atomicAdd(Cf + (size_t)(row + 8) * ldc + col,     acc[mi][ni][2]);
                atomicAdd(Cf + (size_t)(row + 8) * ldc + col + 1, acc[mi][ni][3]);
            }
        }
    }
}

// ============================================================================
// Launch: prep_p, prep_rest, GEMM1+aux, GEMM2-SK (#4 = ncu capture)
// ============================================================================
extern "C" void kernel_launch(void* const* d_in, const int* in_sizes, int n_in,
                              void* d_out, int out_size) {
    (void)in_sizes; (void)n_in; (void)out_size;
    const float* x    = (const float*)d_in[0];
    const float* Pi   = (const float*)d_in[1];
    const int*   idx1 = (const int*)  d_in[2];
    const float* nrm1 = (const float*)d_in[3];
    const float* cb1  = (const float*)d_in[4];
    const int*   idx2 = (const int*)  d_in[5];
    const float* nrm2 = (const float*)d_in[6];
    const float* cb2  = (const float*)d_in[7];
    const float* Pi2  = (const float*)d_in[8];
    float* out = (float*)d_out;

    __half *px16, *pP16, *pW16, *pxr;
    cudaGetSymbolAddress((void**)&px16, g_x16);
    cudaGetSymbolAddress((void**)&pP16, g_P16);
    cudaGetSymbolAddress((void**)&pW16, g_W16);
    cudaGetSymbolAddress((void**)&pxr,  g_xr);

    cudaFuncSetAttribute(tq_hgemm_aux, cudaFuncAttributeMaxDynamicSharedMemorySize,
                         SMEM_BYTES);
    cudaFuncSetAttribute(tq_hgemm2_sk, cudaFuncAttributeMaxDynamicSharedMemorySize,
                         SMEM_BYTES);

    // launch 1: Pi + Pi2 -> fp16
    tq_prep_p<<<8192, 256>>>((const float4*)Pi, (const float4*)Pi2, (__half2*)pP16);

    // launch 2: x -> fp16, dequant pass 2, zero out
    tq_prep_rest<<<5120, 256>>>((const float4*)x, (__half2*)px16,
                                (const int4*)idx2, nrm2, cb2, pW16,
                                (float4*)out);

    // launch 3: GEMM1 (256 CTAs) + 40 aux CTAs (dq1)
    //   xr[512, 8192] = x16 @ Pcat^T  (K = 4096)
    {
        dim3 grid(TOK / TT, 2 * NF / TJ + AUX_Y, 1);   // (4, 74) = 296 CTAs
        tq_hgemm_aux<<<grid, 256, SMEM_BYTES>>>(
            px16, NF, pP16, NF, NF / KSTEP, 2 * NF / TJ, pxr, 2 * NF,
            (const int4*)idx1, nrm1, cb1, pW16);
    }

    // launch 4 (ncu capture): GEMM2 stream-K  out += xr @ Wcat^T  (K = 8192)
    tq_hgemm2_sk<<<SK_CTAS, 256, SMEM_BYTES>>>(pxr, 2 * NF, pW16, 2 * NF, out, NF);
}

// round 15
// speedup vs baseline: 1.0238x; 1.0238x over previous
#include <cuda_runtime.h>
#include <cuda_fp16.h>
#include <cstdint>
#include <cstddef>

// ============================================================================
//   out[t,m] = sum_j xr[t,j] * Wcat[m,j],  xr = [x@Pi1^T | x@Pi2^T]  (K = 8192)
//   xr[t,j]  = sum_k x[t,k]  * Pcat[j,k]   (Pcat = [Pi1; Pi2], N = 8192, K = 4096)
// ============================================================================
#define TOK    512
#define NF     4096
#define KSTEP  64                          // halves of K per stage (128 B rows)
#define NSTG   3
#define TT     128
#define TJ     128
#define STAGE_ROWS (TT + TJ)               // 256
#define STAGE_BYTES (STAGE_ROWS * 128)     // 32768
#define SMEM_BYTES  (NSTG * STAGE_BYTES)   // 98304 -> 2 CTAs/SM
#define AUX_Y   10                         // 40 aux CTAs inside GEMM1 launch

// ============================================================================
// Device scratch (no cudaMalloc allowed)
// ============================================================================
static __device__ __half g_x16[(size_t)TOK * NF];          //  4 MB
static __device__ __half g_P16[(size_t)2 * NF * NF];       // 64 MB  [Pi1; Pi2]
static __device__ __half g_W16[(size_t)NF * 2 * NF];       // 64 MB  [W1 | W2] per row
static __device__ __half g_xr [(size_t)TOK * 2 * NF];      //  8 MB  [xr1 | xr2]

static __device__ __forceinline__ uint32_t smem_u32(const void* p) {
    uint32_t a;
    asm("{ .reg .u64 t; cvta.to.shared.u64 t, %1; cvt.u32.u64 %0, t; }"
        : "=r"(a) : "l"(p));
    return a;
}

#define TQ_LDSM4(r0, r1, r2, r3, addr) \
    asm volatile("ldmatrix.sync.aligned.m8n8.x4.shared.b16 {%0,%1,%2,%3}, [%4];" \
                 : "=r"(r0), "=r"(r1), "=r"(r2), "=r"(r3) : "r"(addr))

// ============================================================================
// Prep kernel A: Pi + Pi2 fp32 -> fp16 (192 MB traffic, DRAM-cap bound)
// ============================================================================
__global__ void tq_prep_p(const float4* __restrict__ Pi, const float4* __restrict__ Pi2,
                          __half2* __restrict__ P16) {
    const int n4 = NF * NF / 4;
    int i = blockIdx.x * 1024 + threadIdx.x;
    #pragma unroll
    for (int j = 0; j < 4; ++j) {
        int k = i + j * 256;
        float4 v = (k < n4) ? Pi[k] : Pi2[k - n4];
        P16[2 * k]     = __floats2half2_rn(v.x, v.y);
        P16[2 * k + 1] = __floats2half2_rn(v.z, v.w);
    }
}

// ============================================================================
// Prep kernel B (block-range dispatch, 5120 blocks):
//   [0, 512)      : x fp32 -> fp16
//   [512, 4608)   : dequant pass 2 -> g_W16[:, NF:]
//   [4608, 5120)  : zero fp32 output (atomicAdd target of GEMM2)
// ============================================================================
__global__ void tq_prep_rest(const float4* __restrict__ x, __half2* __restrict__ x16,
                             const int4* __restrict__ IP4, const float* __restrict__ NRM,
                             const float* __restrict__ CB, __half* __restrict__ W16,
                             float4* __restrict__ zo)
{
    const int b = blockIdx.x;
    if (b < 512) {                        // --- x conversion (10 MB)
        int i = b * 1024 + threadIdx.x;
        #pragma unroll
        for (int j = 0; j < 4; ++j) {
            int k = i + j * 256;
            float4 v = x[k];
            x16[2 * k]     = __floats2half2_rn(v.x, v.y);
            x16[2 * k + 1] = __floats2half2_rn(v.z, v.w);
        }
    } else if (b < 4608) {                // --- dequant pass 2 (64 MB)
        __shared__ float cb[16];
        if (threadIdx.x < 16) cb[threadIdx.x] = CB[threadIdx.x];
        __syncthreads();
        int base = (b - 512) * 512 + threadIdx.x;
        #pragma unroll
        for (int u = 0; u < 2; ++u) {
            int i = base + u * 256;
            int m  = i >> 9;
            int c4 = i & 511;
            int4 p = IP4[i];
            float s = __ldg(&NRM[(m << 5) + (c4 >> 4)]) * 0.08838834764831843f;
            __half2 h[4];
            h[0] = __floats2half2_rn(cb[p.x & 15] * s, cb[(p.x >> 4) & 15] * s);
            h[1] = __floats2half2_rn(cb[p.y & 15] * s, cb[(p.y >> 4) & 15] * s);
            h[2] = __floats2half2_rn(cb[p.z & 15] * s, cb[(p.z >> 4) & 15] * s);
            h[3] = __floats2half2_rn(cb[p.w & 15] * s, cb[(p.w >> 4) & 15] * s);
            *reinterpret_cast<uint4*>(W16 + (size_t)m * (2 * NF) + NF + c4 * 8) =
                *reinterpret_cast<uint4*>(h);
        }
    } else {                              // --- zero out (8 MB)
        int i = (b - 4608) * 1024 + threadIdx.x;
        #pragma unroll
        for (int j = 0; j < 4; ++j)
            zo[i + j * 256] = make_float4(0.f, 0.f, 0.f, 0.f);
    }
}

// ============================================================================
// GEMM1 + aux (r12/r13 exact, measured): tile 128x128, 8 warps, warp 64x32,
//   3-stage cp.async, fragment double-buffered; aux CTAs run dq pass 1.
// ============================================================================
__global__ void __launch_bounds__(256, 2)
tq_hgemm_aux(const __half* __restrict__ X, int ldx,
             const __half* __restrict__ W, int ldw,
             int ksteps, int jTiles, __half* __restrict__ Ch, int ldc,
             const int4* __restrict__ dq_i1, const float* __restrict__ dq_n1,
             const float* __restrict__ dq_c1, __half* __restrict__ dq_out)
{
    extern __shared__ __align__(1024) char dsm[];

    // ---------------- aux path: dq1 (64 MB over 40 CTAs) --------------------
    if ((int)blockIdx.y >= jTiles) {
        float* cb = reinterpret_cast<float*>(dsm);
        if (threadIdx.x < 16) cb[threadIdx.x] = dq_c1[threadIdx.x];
        __syncthreads();
        const int auxId  = (blockIdx.y - jTiles) * gridDim.x + blockIdx.x;
        const int nAux   = AUX_Y * gridDim.x;
        const int total   = NF * (NF / 2) / 4;
        const int start4  = (auxId * 256 + threadIdx.x) * 4;
        const int stride4 = nAux * 256 * 4;
        for (int i0 = start4; i0 < total; i0 += stride4) {
            int4 p[4];
            #pragma unroll
            for (int u = 0; u < 4; ++u) p[u] = dq_i1[i0 + u];
            #pragma unroll
            for (int u = 0; u < 4; ++u) {
                int i  = i0 + u;
                int m  = i >> 9;
                int c4 = i & 511;
                float s = __ldg(&dq_n1[(m << 5) + (c4 >> 4)]) * 0.08838834764831843f;
                __half2 h[4];
                h[0] = __floats2half2_rn(cb[p[u].x & 15] * s, cb[(p[u].x >> 4) & 15] * s);
                h[1] = __floats2half2_rn(cb[p[u].y & 15] * s, cb[(p[u].y >> 4) & 15] * s);
                h[2] = __floats2half2_rn(cb[p[u].z & 15] * s, cb[(p[u].z >> 4) & 15] * s);
                h[3] = __floats2half2_rn(cb[p[u].w & 15] * s, cb[(p[u].w >> 4) & 15] * s);
                *reinterpret_cast<uint4*>(dq_out + (size_t)m * (2 * NF) + c4 * 8) =
                    *reinterpret_cast<uint4*>(h);
            }
        }
        return;
    }

    // ---------------- GEMM path --------------------------------------------
    const uint32_t smBase = smem_u32(dsm);
    const int tid = threadIdx.x;
    const int wid = tid >> 5;
    const int lid = tid & 31;
    const int wm  = wid >> 2;
    const int wn  = wid & 3;
    const int tBase = blockIdx.x * TT;
    const int jBase = blockIdx.y * TJ;

    const __half* xb = X + (size_t)tBase * ldx;
    const __half* wb = W + (size_t)jBase * ldw;

    auto load_stage = [&](int slot, int step) {
        const int k0 = step * KSTEP;
        #pragma unroll
        for (int s = 0; s < 8; ++s) {
            int q = tid + s * 256;
            int r = q >> 3;
            int c = q & 7;
            const __half* src = (r < TT ? xb + (size_t)r * ldx
                                        : wb + (size_t)(r - TT) * ldw) + k0 + c * 8;
            uint32_t dst = smBase + slot * STAGE_BYTES + r * 128 + ((c ^ (r & 7)) * 16);
            asm volatile("cp.async.cg.shared.global [%0], [%1], 16;"
                         :: "r"(dst), "l"(src));
        }
    };

    const int swz  = lid & 7;
    const int rowA = wm * 64 + (lid & 7) + ((lid >> 3) & 1) * 8;
    const int pA   = lid >> 4;
    const int rowB = TT + wn * 32 + (lid & 7) + ((lid >> 4) & 1) * 8;
    const int pB   = (lid >> 3) & 1;

    float acc[4][4][4];
    #pragma unroll
    for (int a = 0; a < 4; ++a)
        #pragma unroll
        for (int b = 0; b < 4; ++b)
            #pragma unroll
            for (int c = 0; c < 4; ++c) acc[a][b][c] = 0.f;

    load_stage(0, 0);
    asm volatile("cp.async.commit_group;" ::: "memory");
    load_stage(1, 1);
    asm volatile("cp.async.commit_group;" ::: "memory");

    uint32_t a[2][4][4];
    uint32_t b[2][4][2];

    auto ldfrag = [&](int buf, uint32_t sb, int kb) {
        #pragma unroll
        for (int mi = 0; mi < 4; ++mi) {
            uint32_t ad = sb + (uint32_t)(rowA + mi * 16) * 128
                        + (uint32_t)(((kb * 2 + pA) ^ swz) * 16);
            TQ_LDSM4(a[buf][mi][0], a[buf][mi][1], a[buf][mi][2], a[buf][mi][3], ad);
        }
        #pragma unroll
        for (int gi = 0; gi < 2; ++gi) {
            uint32_t bd = sb + (uint32_t)(rowB + gi * 16) * 128
                        + (uint32_t)(((kb * 2 + pB) ^ swz) * 16);
            TQ_LDSM4(b[buf][2 * gi][0], b[buf][2 * gi][1],
                     b[buf][2 * gi + 1][0], b[buf][2 * gi + 1][1], bd);
        }
    };

    auto domma = [&](int buf) {
        #pragma unroll
        for (int mi = 0; mi < 4; ++mi)
            #pragma unroll
            for (int ni = 0; ni < 4; ++ni) {
                asm volatile(
                    "mma.sync.aligned.m16n8k16.row.col.f32.f16.f16.f32 "
                    "{%0,%1,%2,%3}, {%4,%5,%6,%7}, {%8,%9}, {%0,%1,%2,%3};"
                    : "+f"(acc[mi][ni][0]), "+f"(acc[mi][ni][1]),
                      "+f"(acc[mi][ni][2]), "+f"(acc[mi][ni][3])
                    : "r"(a[buf][mi][0]), "r"(a[buf][mi][1]),
                      "r"(a[buf][mi][2]), "r"(a[buf][mi][3]),
                      "r"(b[buf][ni][0]), "r"(b[buf][ni][1]));
            }
    };

    int slot = 0, pfslot = 2;
    for (int it = 0; it < ksteps; ++it) {
        asm volatile("cp.async.wait_group 1;" ::: "memory");
        __syncthreads();

        const int pf = it + NSTG - 1;
        if (pf < ksteps) load_stage(pfslot, pf);
        asm volatile("cp.async.commit_group;" ::: "memory");

        const uint32_t sb = smBase + slot * STAGE_BYTES;
        if (++slot == NSTG) slot = 0;
        if (++pfslot == NSTG) pfslot = 0;

        ldfrag(0, sb, 0);
        #pragma unroll
        for (int kb = 0; kb < 4; ++kb) {
            const int cur = kb & 1;
            if (kb < 3) ldfrag(cur ^ 1, sb, kb + 1);
            domma(cur);
        }
    }

    const int g  = lid >> 2;
    const int tg = lid & 3;
    #pragma unroll
    for (int mi = 0; mi < 4; ++mi) {
        #pragma unroll
        for (int ni = 0; ni < 4; ++ni) {
            int row = tBase + wm * 64 + mi * 16 + g;
            int col = jBase + wn * 32 + ni * 8 + tg * 2;
            __half2 h0 = __floats2half2_rn(acc[mi][ni][0], acc[mi][ni][1]);
            __half2 h1 = __floats2half2_rn(acc[mi][ni][2], acc[mi][ni][3]);
            *reinterpret_cast<__half2*>(Ch + (size_t)row * ldc + col)       = h0;
            *reinterpret_cast<__half2*>(Ch + (size_t)(row + 8) * ldc + col) = h1;
        }
    }
}

// ============================================================================
// GEMM2, 4-warp variant: 128 threads, warp grid 2(t) x 2(j), warp tile 64x64.
//   Halves LDSM crossbar traffic vs the 8-warp 64x32 layout (A redundancy
//   4x -> 2x). acc 128 regs + double-buffered frags (~215 regs, cap 256).
//   Split-K 2 (z), fp32 atomicAdd epilogue. Same smem layout / swizzle.
// ============================================================================
__global__ void __launch_bounds__(128, 2)
tq_hgemm2_w4(const __half* __restrict__ X, int ldx,
             const __half* __restrict__ W, int ldw,
             int ksteps, float* __restrict__ Cf, int ldc)
{
    extern __shared__ __align__(1024) char dsm[];
    const uint32_t smBase = smem_u32(dsm);

    const int tid = threadIdx.x;
    const int wid = tid >> 5;            // 0..3
    const int lid = tid & 31;
    const int wm  = wid >> 1;            // 0..1
    const int wn  = wid & 1;             // 0..1
    const int tBase = blockIdx.x * TT;
    const int jBase = blockIdx.y * TJ;
    const int kOff  = blockIdx.z * (ksteps * KSTEP);

    const __half* xb = X + (size_t)tBase * ldx + kOff;
    const __half* wb = W + (size_t)jBase * ldw + kOff;

    // stage loader: 2048 chunks over 128 threads = 16 per thread
    auto load_stage = [&](int slot, int step) {
        const int k0 = step * KSTEP;
        #pragma unroll
        for (int s = 0; s < 16; ++s) {
            int q = tid + s * 128;
            int r = q >> 3;
            int c = q & 7;
            const __half* src = (r < TT ? xb + (size_t)r * ldx
                                        : wb + (size_t)(r - TT) * ldw) + k0 + c * 8;
            uint32_t dst = smBase + slot * STAGE_BYTES + r * 128 + ((c ^ (r & 7)) * 16);
            asm volatile("cp.async.cg.shared.global [%0], [%1], 16;"
                         :: "r"(dst), "l"(src));
        }
    };

    const int swz  = lid & 7;
    const int rowA = wm * 64 + (lid & 7) + ((lid >> 3) & 1) * 8;
    const int pA   = lid >> 4;
    const int rowB = TT + wn * 64 + (lid & 7) + ((lid >> 4) & 1) * 8;
    const int pB   = (lid >> 3) & 1;

    float acc[4][8][4];
    #pragma unroll
    for (int ia = 0; ia < 4; ++ia)
        #pragma unroll
        for (int ib = 0; ib < 8; ++ib)
            #pragma unroll
            for (int ic = 0; ic < 4; ++ic) acc[ia][ib][ic] = 0.f;

    load_stage(0, 0);
    asm volatile("cp.async.commit_group;" ::: "memory");
    load_stage(1, 1);
    asm volatile("cp.async.commit_group;" ::: "memory");

    uint32_t a[2][4][4];
    uint32_t b[2][8][2];

    auto ldfrag = [&](int buf, uint32_t sb, int kb) {
        #pragma unroll
        for (int mi = 0; mi < 4; ++mi) {
            uint32_t ad = sb + (uint32_t)(rowA + mi * 16) * 128
                        + (uint32_t)(((kb * 2 + pA) ^ swz) * 16);
            TQ_LDSM4(a[buf][mi][0], a[buf][mi][1], a[buf][mi][2], a[buf][mi][3], ad);
        }
        #pragma unroll
        for (int gi = 0; gi < 4; ++gi) {
            uint32_t bd = sb + (uint32_t)(rowB + gi * 16) * 128
                        + (uint32_t)(((kb * 2 + pB) ^ swz) * 16);
            TQ_LDSM4(b[buf][2 * gi][0], b[buf][2 * gi][1],
                     b[buf][2 * gi + 1][0], b[buf][2 * gi + 1][1], bd);
        }
    };

    auto domma = [&](int buf) {
        #pragma unroll
        for (int mi = 0; mi < 4; ++mi)
            #pragma unroll
            for (int ni = 0; ni < 8; ++ni) {
                asm volatile(
                    "mma.sync.aligned.m16n8k16.row.col.f32.f16.f16.f32 "
                    "{%0,%1,%2,%3}, {%4,%5,%6,%7}, {%8,%9}, {%0,%1,%2,%3};"
                    : "+f"(acc[mi][ni][0]), "+f"(acc[mi][ni][1]),
                      "+f"(acc[mi][ni][2]), "+f"(acc[mi][ni][3])
                    : "r"(a[buf][mi][0]), "r"(a[buf][mi][1]),
                      "r"(a[buf][mi][2]), "r"(a[buf][mi][3]),
                      "r"(b[buf][ni][0]), "r"(b[buf][ni][1]));
            }
    };

    int slot = 0, pfslot = 2;
    for (int it = 0; it < ksteps; ++it) {
        asm volatile("cp.async.wait_group 1;" ::: "memory");
        __syncthreads();

        const int pf = it + NSTG - 1;
        if (pf < ksteps) load_stage(pfslot, pf);
        asm volatile("cp.async.commit_group;" ::: "memory");

        const uint32_t sb = smBase + slot * STAGE_BYTES;
        if (++slot == NSTG) slot = 0;
        if (++pfslot == NSTG) pfslot = 0;

        ldfrag(0, sb, 0);
        #pragma unroll
        for (int kb = 0; kb < 4; ++kb) {
            const int cur = kb & 1;
            if (kb < 3) ldfrag(cur ^ 1, sb, kb + 1);
            domma(cur);
        }
    }

    const int g  = lid >> 2;
    const int tg = lid & 3;
    #pragma unroll
    for (int mi = 0; mi < 4; ++mi) {
        #pragma unroll
        for (int ni = 0; ni < 8; ++ni) {
            int row = tBase + wm * 64 + mi * 16 + g;
            int col = jBase + wn * 64 + ni * 8 + tg * 2;
            atomicAdd(Cf + (size_t)row * ldc + col,           acc[mi][ni][0]);
            atomicAdd(Cf + (size_t)row * ldc + col + 1,       acc[mi][ni][1]);
            atomicAdd(Cf + (size_t)(row + 8) * ldc + col,     acc[mi][ni][2]);
            atomicAdd(Cf + (size_t)(row + 8) * ldc + col + 1, acc[mi][ni][3]);
        }
    }
}

// ============================================================================
// Launch: prep_p, prep_rest, GEMM1+aux, GEMM2-w4 (#4 = ncu capture)
// ============================================================================
extern "C" void kernel_launch(void* const* d_in, const int* in_sizes, int n_in,
                              void* d_out, int out_size) {
    (void)in_sizes; (void)n_in; (void)out_size;
    const float* x    = (const float*)d_in[0];
    const float* Pi   = (const float*)d_in[1];
    const int*   idx1 = (const int*)  d_in[2];
    const float* nrm1 = (const float*)d_in[3];
    const float* cb1  = (const float*)d_in[4];
    const int*   idx2 = (const int*)  d_in[5];
    const float* nrm2 = (const float*)d_in[6];
    const float* cb2  = (const float*)d_in[7];
    const float* Pi2  = (const float*)d_in[8];
    float* out = (float*)d_out;

    __half *px16, *pP16, *pW16, *pxr;
    cudaGetSymbolAddress((void**)&px16, g_x16);
    cudaGetSymbolAddress((void**)&pP16, g_P16);
    cudaGetSymbolAddress((void**)&pW16, g_W16);
    cudaGetSymbolAddress((void**)&pxr,  g_xr);

    cudaFuncSetAttribute(tq_hgemm_aux, cudaFuncAttributeMaxDynamicSharedMemorySize,
                         SMEM_BYTES);
    cudaFuncSetAttribute(tq_hgemm2_w4, cudaFuncAttributeMaxDynamicSharedMemorySize,
                         SMEM_BYTES);

    // launch 1: Pi + Pi2 -> fp16
    tq_prep_p<<<8192, 256>>>((const float4*)Pi, (const float4*)Pi2, (__half2*)pP16);

    // launch 2: x -> fp16, dequant pass 2, zero out
    tq_prep_rest<<<5120, 256>>>((const float4*)x, (__half2*)px16,
                                (const int4*)idx2, nrm2, cb2, pW16,
                                (float4*)out);

    // launch 3: GEMM1 (256 CTAs) + 40 aux CTAs (dq1)
    //   xr[512, 8192] = x16 @ Pcat^T  (K = 4096)
    {
        dim3 grid(TOK / TT, 2 * NF / TJ + AUX_Y, 1);   // (4, 74) = 296 CTAs
        tq_hgemm_aux<<<grid, 256, SMEM_BYTES>>>(
            px16, NF, pP16, NF, NF / KSTEP, 2 * NF / TJ, pxr, 2 * NF,
            (const int4*)idx1, nrm1, cb1, pW16);
    }

    // launch 4 (ncu capture): GEMM2 4-warp  out += xr @ Wcat^T  (K = 8192, split-K 2)
    {
        dim3 grid(TOK / TT, NF / TJ, 2);               // (4, 32, 2) = 256 CTAs
        tq_hgemm2_w4<<<grid, 128, SMEM_BYTES>>>(pxr, 2 * NF, pW16, 2 * NF,
                                                (2 * NF / KSTEP) / 2, out, NF);
    }
}

// round 16
// speedup vs baseline: 1.0468x; 1.0225x over previous
#include <cuda_runtime.h>
#include <cuda_fp16.h>
#include <cstdint>
#include <cstddef>

// ============================================================================
//   out[t,m] = sum_j xr[t,j] * Wcat[m,j],  xr = [x@Pi1^T | x@Pi2^T]  (K = 8192)
//   xr[t,j]  = sum_k x[t,k]  * Pcat[j,k]   (Pcat = [Pi1; Pi2], N = 8192, K = 4096)
// ============================================================================
#define TOK    512
#define NF     4096
#define KSTEP  64                          // halves of K per stage (128 B rows)
#define NSTG   3
#define TT     128
#define TJ     128
#define STAGE_ROWS (TT + TJ)               // 256
#define STAGE_BYTES (STAGE_ROWS * 128)     // 32768
#define SMEM_BYTES  (NSTG * STAGE_BYTES)   // 98304 -> 2 CTAs/SM
#define AUX_Y   10                         // 40 aux CTAs inside GEMM1 launch

// ============================================================================
// Device scratch (no cudaMalloc allowed)
// ============================================================================
static __device__ __half g_x16[(size_t)TOK * NF];          //  4 MB
static __device__ __half g_P16[(size_t)2 * NF * NF];       // 64 MB  [Pi1; Pi2]
static __device__ __half g_W16[(size_t)NF * 2 * NF];       // 64 MB  [W1 | W2] per row
static __device__ __half g_xr [(size_t)TOK * 2 * NF];      //  8 MB  [xr1 | xr2]

static __device__ __forceinline__ uint32_t smem_u32(const void* p) {
    uint32_t a;
    asm("{ .reg .u64 t; cvta.to.shared.u64 t, %1; cvt.u32.u64 %0, t; }"
        : "=r"(a) : "l"(p));
    return a;
}

#define TQ_LDSM4(r0, r1, r2, r3, addr) \
    asm volatile("ldmatrix.sync.aligned.m8n8.x4.shared.b16 {%0,%1,%2,%3}, [%4];" \
                 : "=r"(r0), "=r"(r1), "=r"(r2), "=r"(r3) : "r"(addr))

// ============================================================================
// Prep kernel A: Pi + Pi2 fp32 -> fp16 (192 MB traffic, DRAM-cap bound)
// ============================================================================
__global__ void tq_prep_p(const float4* __restrict__ Pi, const float4* __restrict__ Pi2,
                          __half2* __restrict__ P16) {
    const int n4 = NF * NF / 4;
    int i = blockIdx.x * 1024 + threadIdx.x;
    #pragma unroll
    for (int j = 0; j < 4; ++j) {
        int k = i + j * 256;
        float4 v = (k < n4) ? Pi[k] : Pi2[k - n4];
        P16[2 * k]     = __floats2half2_rn(v.x, v.y);
        P16[2 * k + 1] = __floats2half2_rn(v.z, v.w);
    }
}

// ============================================================================
// Prep kernel B (block-range dispatch, 5120 blocks):
//   [0, 512)      : x fp32 -> fp16
//   [512, 4608)   : dequant pass 2 -> g_W16[:, NF:]
//   [4608, 5120)  : zero fp32 output (atomicAdd target of GEMM2)
// ============================================================================
__global__ void tq_prep_rest(const float4* __restrict__ x, __half2* __restrict__ x16,
                             const int4* __restrict__ IP4, const float* __restrict__ NRM,
                             const float* __restrict__ CB, __half* __restrict__ W16,
                             float4* __restrict__ zo)
{
    const int b = blockIdx.x;
    if (b < 512) {                        // --- x conversion (10 MB)
        int i = b * 1024 + threadIdx.x;
        #pragma unroll
        for (int j = 0; j < 4; ++j) {
            int k = i + j * 256;
            float4 v = x[k];
            x16[2 * k]     = __floats2half2_rn(v.x, v.y);
            x16[2 * k + 1] = __floats2half2_rn(v.z, v.w);
        }
    } else if (b < 4608) {                // --- dequant pass 2 (64 MB)
        __shared__ float cb[16];
        if (threadIdx.x < 16) cb[threadIdx.x] = CB[threadIdx.x];
        __syncthreads();
        int base = (b - 512) * 512 + threadIdx.x;
        #pragma unroll
        for (int u = 0; u < 2; ++u) {
            int i = base + u * 256;
            int m  = i >> 9;
            int c4 = i & 511;
            int4 p = IP4[i];
            float s = __ldg(&NRM[(m << 5) + (c4 >> 4)]) * 0.08838834764831843f;
            __half2 h[4];
            h[0] = __floats2half2_rn(cb[p.x & 15] * s, cb[(p.x >> 4) & 15] * s);
            h[1] = __floats2half2_rn(cb[p.y & 15] * s, cb[(p.y >> 4) & 15] * s);
            h[2] = __floats2half2_rn(cb[p.z & 15] * s, cb[(p.z >> 4) & 15] * s);
            h[3] = __floats2half2_rn(cb[p.w & 15] * s, cb[(p.w >> 4) & 15] * s);
            *reinterpret_cast<uint4*>(W16 + (size_t)m * (2 * NF) + NF + c4 * 8) =
                *reinterpret_cast<uint4*>(h);
        }
    } else {                              // --- zero out (8 MB)
        int i = (b - 4608) * 1024 + threadIdx.x;
        #pragma unroll
        for (int j = 0; j < 4; ++j)
            zo[i + j * 256] = make_float4(0.f, 0.f, 0.f, 0.f);
    }
}

// ============================================================================
// GEMM1 4-warp + aux: 128 threads, warp grid 2(t) x 2(j), warp tile 64x64,
//   3-stage cp.async, fragment double-buffered; fp16 store epilogue.
//   Aux CTAs (blockIdx.y >= jTiles): dequant pass 1 (64 MB, MLP 6, guarded).
// ============================================================================
__global__ void __launch_bounds__(128, 2)
tq_hgemm1_w4(const __half* __restrict__ X, int ldx,
             const __half* __restrict__ W, int ldw,
             int ksteps, int jTiles, __half* __restrict__ Ch, int ldc,
             const int4* __restrict__ dq_i1, const float* __restrict__ dq_n1,
             const float* __restrict__ dq_c1, __half* __restrict__ dq_out)
{
    extern __shared__ __align__(1024) char dsm[];

    // ---------------- aux path: dq1 (64 MB over 40 x 128-thread CTAs) -------
    if ((int)blockIdx.y >= jTiles) {
        float* cb = reinterpret_cast<float*>(dsm);
        if (threadIdx.x < 16) cb[threadIdx.x] = dq_c1[threadIdx.x];
        __syncthreads();
        const int auxId  = (blockIdx.y - jTiles) * gridDim.x + blockIdx.x;
        const int nAux   = AUX_Y * gridDim.x;        // 40
        const int total   = NF * (NF / 2) / 4;       // 2M int4
        const int start6  = (auxId * 128 + threadIdx.x) * 6;
        const int stride6 = nAux * 128 * 6;
        for (int i0 = start6; i0 < total; i0 += stride6) {
            int4 p[6];
            #pragma unroll
            for (int u = 0; u < 6; ++u)
                p[u] = (i0 + u < total) ? dq_i1[i0 + u] : make_int4(0, 0, 0, 0);
            #pragma unroll
            for (int u = 0; u < 6; ++u) {
                int i = i0 + u;
                if (i >= total) break;
                int m  = i >> 9;
                int c4 = i & 511;
                float s = __ldg(&dq_n1[(m << 5) + (c4 >> 4)]) * 0.08838834764831843f;
                __half2 h[4];
                h[0] = __floats2half2_rn(cb[p[u].x & 15] * s, cb[(p[u].x >> 4) & 15] * s);
                h[1] = __floats2half2_rn(cb[p[u].y & 15] * s, cb[(p[u].y >> 4) & 15] * s);
                h[2] = __floats2half2_rn(cb[p[u].z & 15] * s, cb[(p[u].z >> 4) & 15] * s);
                h[3] = __floats2half2_rn(cb[p[u].w & 15] * s, cb[(p[u].w >> 4) & 15] * s);
                *reinterpret_cast<uint4*>(dq_out + (size_t)m * (2 * NF) + c4 * 8) =
                    *reinterpret_cast<uint4*>(h);
            }
        }
        return;
    }

    // ---------------- GEMM path (w4, same as measured GEMM2-w4) -------------
    const uint32_t smBase = smem_u32(dsm);
    const int tid = threadIdx.x;
    const int wid = tid >> 5;
    const int lid = tid & 31;
    const int wm  = wid >> 1;
    const int wn  = wid & 1;
    const int tBase = blockIdx.x * TT;
    const int jBase = blockIdx.y * TJ;

    const __half* xb = X + (size_t)tBase * ldx;
    const __half* wb = W + (size_t)jBase * ldw;

    auto load_stage = [&](int slot, int step) {
        const int k0 = step * KSTEP;
        #pragma unroll
        for (int s = 0; s < 16; ++s) {
            int q = tid + s * 128;
            int r = q >> 3;
            int c = q & 7;
            const __half* src = (r < TT ? xb + (size_t)r * ldx
                                        : wb + (size_t)(r - TT) * ldw) + k0 + c * 8;
            uint32_t dst = smBase + slot * STAGE_BYTES + r * 128 + ((c ^ (r & 7)) * 16);
            asm volatile("cp.async.cg.shared.global [%0], [%1], 16;"
                         :: "r"(dst), "l"(src));
        }
    };

    const int swz  = lid & 7;
    const int rowA = wm * 64 + (lid & 7) + ((lid >> 3) & 1) * 8;
    const int pA   = lid >> 4;
    const int rowB = TT + wn * 64 + (lid & 7) + ((lid >> 4) & 1) * 8;
    const int pB   = (lid >> 3) & 1;

    float acc[4][8][4];
    #pragma unroll
    for (int ia = 0; ia < 4; ++ia)
        #pragma unroll
        for (int ib = 0; ib < 8; ++ib)
            #pragma unroll
            for (int ic = 0; ic < 4; ++ic) acc[ia][ib][ic] = 0.f;

    load_stage(0, 0);
    asm volatile("cp.async.commit_group;" ::: "memory");
    load_stage(1, 1);
    asm volatile("cp.async.commit_group;" ::: "memory");

    uint32_t a[2][4][4];
    uint32_t b[2][8][2];

    auto ldfrag = [&](int buf, uint32_t sb, int kb) {
        #pragma unroll
        for (int mi = 0; mi < 4; ++mi) {
            uint32_t ad = sb + (uint32_t)(rowA + mi * 16) * 128
                        + (uint32_t)(((kb * 2 + pA) ^ swz) * 16);
            TQ_LDSM4(a[buf][mi][0], a[buf][mi][1], a[buf][mi][2], a[buf][mi][3], ad);
        }
        #pragma unroll
        for (int gi = 0; gi < 4; ++gi) {
            uint32_t bd = sb + (uint32_t)(rowB + gi * 16) * 128
                        + (uint32_t)(((kb * 2 + pB) ^ swz) * 16);
            TQ_LDSM4(b[buf][2 * gi][0], b[buf][2 * gi][1],
                     b[buf][2 * gi + 1][0], b[buf][2 * gi + 1][1], bd);
        }
    };

    auto domma = [&](int buf) {
        #pragma unroll
        for (int mi = 0; mi < 4; ++mi)
            #pragma unroll
            for (int ni = 0; ni < 8; ++ni) {
                asm volatile(
                    "mma.sync.aligned.m16n8k16.row.col.f32.f16.f16.f32 "
                    "{%0,%1,%2,%3}, {%4,%5,%6,%7}, {%8,%9}, {%0,%1,%2,%3};"
                    : "+f"(acc[mi][ni][0]), "+f"(acc[mi][ni][1]),
                      "+f"(acc[mi][ni][2]), "+f"(acc[mi][ni][3])
                    : "r"(a[buf][mi][0]), "r"(a[buf][mi][1]),
                      "r"(a[buf][mi][2]), "r"(a[buf][mi][3]),
                      "r"(b[buf][ni][0]), "r"(b[buf][ni][1]));
            }
    };

    int slot = 0, pfslot = 2;
    for (int it = 0; it < ksteps; ++it) {
        asm volatile("cp.async.wait_group 1;" ::: "memory");
        __syncthreads();

        const int pf = it + NSTG - 1;
        if (pf < ksteps) load_stage(pfslot, pf);
        asm volatile("cp.async.commit_group;" ::: "memory");

        const uint32_t sb = smBase + slot * STAGE_BYTES;
        if (++slot == NSTG) slot = 0;
        if (++pfslot == NSTG) pfslot = 0;

        ldfrag(0, sb, 0);
        #pragma unroll
        for (int kb = 0; kb < 4; ++kb) {
            const int cur = kb & 1;
            if (kb < 3) ldfrag(cur ^ 1, sb, kb + 1);
            domma(cur);
        }
    }

    const int g  = lid >> 2;
    const int tg = lid & 3;
    #pragma unroll
    for (int mi = 0; mi < 4; ++mi) {
        #pragma unroll
        for (int ni = 0; ni < 8; ++ni) {
            int row = tBase + wm * 64 + mi * 16 + g;
            int col = jBase + wn * 64 + ni * 8 + tg * 2;
            __half2 h0 = __floats2half2_rn(acc[mi][ni][0], acc[mi][ni][1]);
            __half2 h1 = __floats2half2_rn(acc[mi][ni][2], acc[mi][ni][3]);
            *reinterpret_cast<__half2*>(Ch + (size_t)row * ldc + col)       = h0;
            *reinterpret_cast<__half2*>(Ch + (size_t)(row + 8) * ldc + col) = h1;
        }
    }
}

// ============================================================================
// GEMM2 4-warp (r15 exact, measured 92.9 us): split-K 2, atomicAdd epilogue.
// ============================================================================
__global__ void __launch_bounds__(128, 2)
tq_hgemm2_w4(const __half* __restrict__ X, int ldx,
             const __half* __restrict__ W, int ldw,
             int ksteps, float* __restrict__ Cf, int ldc)
{
    extern __shared__ __align__(1024) char dsm[];
    const uint32_t smBase = smem_u32(dsm);

    const int tid = threadIdx.x;
    const int wid = tid >> 5;
    const int lid = tid & 31;
    const int wm  = wid >> 1;
    const int wn  = wid & 1;
    const int tBase = blockIdx.x * TT;
    const int jBase = blockIdx.y * TJ;
    const int kOff  = blockIdx.z * (ksteps * KSTEP);

    const __half* xb = X + (size_t)tBase * ldx + kOff;
    const __half* wb = W + (size_t)jBase * ldw + kOff;

    auto load_stage = [&](int slot, int step) {
        const int k0 = step * KSTEP;
        #pragma unroll
        for (int s = 0; s < 16; ++s) {
            int q = tid + s * 128;
            int r = q >> 3;
            int c = q & 7;
            const __half* src = (r < TT ? xb + (size_t)r * ldx
                                        : wb + (size_t)(r - TT) * ldw) + k0 + c * 8;
            uint32_t dst = smBase + slot * STAGE_BYTES + r * 128 + ((c ^ (r & 7)) * 16);
            asm volatile("cp.async.cg.shared.global [%0], [%1], 16;"
                         :: "r"(dst), "l"(src));
        }
    };

    const int swz  = lid & 7;
    const int rowA = wm * 64 + (lid & 7) + ((lid >> 3) & 1) * 8;
    const int pA   = lid >> 4;
    const int rowB = TT + wn * 64 + (lid & 7) + ((lid >> 4) & 1) * 8;
    const int pB   = (lid >> 3) & 1;

    float acc[4][8][4];
    #pragma unroll
    for (int ia = 0; ia < 4; ++ia)
        #pragma unroll
        for (int ib = 0; ib < 8; ++ib)
            #pragma unroll
            for (int ic = 0; ic < 4; ++ic) acc[ia][ib][ic] = 0.f;

    load_stage(0, 0);
    asm volatile("cp.async.commit_group;" ::: "memory");
    load_stage(1, 1);
    asm volatile("cp.async.commit_group;" ::: "memory");

    uint32_t a[2][4][4];
    uint32_t b[2][8][2];

    auto ldfrag = [&](int buf, uint32_t sb, int kb) {
        #pragma unroll
        for (int mi = 0; mi < 4; ++mi) {
            uint32_t ad = sb + (uint32_t)(rowA + mi * 16) * 128
                        + (uint32_t)(((kb * 2 + pA) ^ swz) * 16);
            TQ_LDSM4(a[buf][mi][0], a[buf][mi][1], a[buf][mi][2], a[buf][mi][3], ad);
        }
        #pragma unroll
        for (int gi = 0; gi < 4; ++gi) {
            uint32_t bd = sb + (uint32_t)(rowB + gi * 16) * 128
                        + (uint32_t)(((kb * 2 + pB) ^ swz) * 16);
            TQ_LDSM4(b[buf][2 * gi][0], b[buf][2 * gi][1],
                     b[buf][2 * gi + 1][0], b[buf][2 * gi + 1][1], bd);
        }
    };

    auto domma = [&](int buf) {
        #pragma unroll
        for (int mi = 0; mi < 4; ++mi)
            #pragma unroll
            for (int ni = 0; ni < 8; ++ni) {
                asm volatile(
                    "mma.sync.aligned.m16n8k16.row.col.f32.f16.f16.f32 "
                    "{%0,%1,%2,%3}, {%4,%5,%6,%7}, {%8,%9}, {%0,%1,%2,%3};"
                    : "+f"(acc[mi][ni][0]), "+f"(acc[mi][ni][1]),
                      "+f"(acc[mi][ni][2]), "+f"(acc[mi][ni][3])
                    : "r"(a[buf][mi][0]), "r"(a[buf][mi][1]),
                      "r"(a[buf][mi][2]), "r"(a[buf][mi][3]),
                      "r"(b[buf][ni][0]), "r"(b[buf][ni][1]));
            }
    };

    int slot = 0, pfslot = 2;
    for (int it = 0; it < ksteps; ++it) {
        asm volatile("cp.async.wait_group 1;" ::: "memory");
        __syncthreads();

        const int pf = it + NSTG - 1;
        if (pf < ksteps) load_stage(pfslot, pf);
        asm volatile("cp.async.commit_group;" ::: "memory");

        const uint32_t sb = smBase + slot * STAGE_BYTES;
        if (++slot == NSTG) slot = 0;
        if (++pfslot == NSTG) pfslot = 0;

        ldfrag(0, sb, 0);
        #pragma unroll
        for (int kb = 0; kb < 4; ++kb) {
            const int cur = kb & 1;
            if (kb < 3) ldfrag(cur ^ 1, sb, kb + 1);
            domma(cur);
        }
    }

    const int g  = lid >> 2;
    const int tg = lid & 3;
    #pragma unroll
    for (int mi = 0; mi < 4; ++mi) {
        #pragma unroll
        for (int ni = 0; ni < 8; ++ni) {
            int row = tBase + wm * 64 + mi * 16 + g;
            int col = jBase + wn * 64 + ni * 8 + tg * 2;
            atomicAdd(Cf + (size_t)row * ldc + col,           acc[mi][ni][0]);
            atomicAdd(Cf + (size_t)row * ldc + col + 1,       acc[mi][ni][1]);
            atomicAdd(Cf + (size_t)(row + 8) * ldc + col,     acc[mi][ni][2]);
            atomicAdd(Cf + (size_t)(row + 8) * ldc + col + 1, acc[mi][ni][3]);
        }
    }
}

// ============================================================================
// Launch: prep_p, prep_rest, GEMM1-w4+aux, GEMM2-w4 (#4 = ncu capture)
// ============================================================================
extern "C" void kernel_launch(void* const* d_in, const int* in_sizes, int n_in,
                              void* d_out, int out_size) {
    (void)in_sizes; (void)n_in; (void)out_size;
    const float* x    = (const float*)d_in[0];
    const float* Pi   = (const float*)d_in[1];
    const int*   idx1 = (const int*)  d_in[2];
    const float* nrm1 = (const float*)d_in[3];
    const float* cb1  = (const float*)d_in[4];
    const int*   idx2 = (const int*)  d_in[5];
    const float* nrm2 = (const float*)d_in[6];
    const float* cb2  = (const float*)d_in[7];
    const float* Pi2  = (const float*)d_in[8];
    float* out = (float*)d_out;

    __half *px16, *pP16, *pW16, *pxr;
    cudaGetSymbolAddress((void**)&px16, g_x16);
    cudaGetSymbolAddress((void**)&pP16, g_P16);
    cudaGetSymbolAddress((void**)&pW16, g_W16);
    cudaGetSymbolAddress((void**)&pxr,  g_xr);

    cudaFuncSetAttribute(tq_hgemm1_w4, cudaFuncAttributeMaxDynamicSharedMemorySize,
                         SMEM_BYTES);
    cudaFuncSetAttribute(tq_hgemm2_w4, cudaFuncAttributeMaxDynamicSharedMemorySize,
                         SMEM_BYTES);

    // launch 1: Pi + Pi2 -> fp16
    tq_prep_p<<<8192, 256>>>((const float4*)Pi, (const float4*)Pi2, (__half2*)pP16);

    // launch 2: x -> fp16, dequant pass 2, zero out
    tq_prep_rest<<<5120, 256>>>((const float4*)x, (__half2*)px16,
                                (const int4*)idx2, nrm2, cb2, pW16,
                                (float4*)out);

    // launch 3: GEMM1-w4 (256 CTAs) + 40 aux CTAs (dq1)
    //   xr[512, 8192] = x16 @ Pcat^T  (K = 4096)
    {
        dim3 grid(TOK / TT, 2 * NF / TJ + AUX_Y, 1);   // (4, 74) = 296 CTAs
        tq_hgemm1_w4<<<grid, 128, SMEM_BYTES>>>(
            px16, NF, pP16, NF, NF / KSTEP, 2 * NF / TJ, pxr, 2 * NF,
            (const int4*)idx1, nrm1, cb1, pW16);
    }

    // launch 4 (ncu capture): GEMM2-w4  out += xr @ Wcat^T  (K = 8192, split-K 2)
    {
        dim3 grid(TOK / TT, NF / TJ, 2);               // (4, 32, 2) = 256 CTAs
        tq_hgemm2_w4<<<grid, 128, SMEM_BYTES>>>(pxr, 2 * NF, pW16, 2 * NF,
                                                (2 * NF / KSTEP) / 2, out, NF);
    }
}

// round 17
// speedup vs baseline: 1.0636x; 1.0161x over previous
#include <cuda_runtime.h>
#include <cuda_fp16.h>
#include <cstdint>
#include <cstddef>

// ============================================================================
//   out[t,m] = sum_j xr[t,j] * Wcat[m,j],  xr = [x@Pi1^T | x@Pi2^T]  (K = 8192)
//   xr[t,j]  = sum_k x[t,k]  * Pcat[j,k]   (Pcat = [Pi1; Pi2], N = 8192, K = 4096)
// ============================================================================
#define TOK    512
#define NF     4096
#define KSTEP  64                          // halves of K per stage (128 B rows)
#define NSTG   3
#define TT     128
#define TJ     128
#define STAGE_ROWS (TT + TJ)               // 256
#define STAGE_BYTES (STAGE_ROWS * 128)     // 32768
#define SMEM_BYTES  (NSTG * STAGE_BYTES)   // 98304 -> 2 CTAs/SM
#define AUX_Y   10                         // 40 aux CTAs inside GEMM1 launch

// ============================================================================
// Device scratch (no cudaMalloc allowed)
// ============================================================================
static __device__ __half g_x16[(size_t)TOK * NF];          //  4 MB
static __device__ __half g_P16[(size_t)2 * NF * NF];       // 64 MB  [Pi1; Pi2]
static __device__ __half g_W16[(size_t)NF * 2 * NF];       // 64 MB  [W1 | W2] per row
static __device__ __half g_xr [(size_t)TOK * 2 * NF];      //  8 MB  [xr1 | xr2]

static __device__ __forceinline__ uint32_t smem_u32(const void* p) {
    uint32_t a;
    asm("{ .reg .u64 t; cvta.to.shared.u64 t, %1; cvt.u32.u64 %0, t; }"
        : "=r"(a) : "l"(p));
    return a;
}

#define TQ_LDSM4(r0, r1, r2, r3, addr) \
    asm volatile("ldmatrix.sync.aligned.m8n8.x4.shared.b16 {%0,%1,%2,%3}, [%4];" \
                 : "=r"(r0), "=r"(r1), "=r"(r2), "=r"(r3) : "r"(addr))

// ============================================================================
// Merged prep kernel (single launch, r13-measured 37.9 us @ 6.35 TB/s):
//   [0, 8192)      : Pi + Pi2 fp32 -> fp16 into g_P16       (192 MB)
//   [8192, 8704)   : x fp32 -> fp16                         (10 MB)
//   [8704, 12800)  : dequant pass 2 -> g_W16[:, NF:]        (64 MB)
//   [12800, 13312) : zero the fp32 output                   (8 MB)
// ============================================================================
#define PREP_BLOCKS 13312

__global__ void tq_prep_all(const float4* __restrict__ Pi, const float4* __restrict__ Pi2,
                            __half2* __restrict__ P16,
                            const float4* __restrict__ x, __half2* __restrict__ x16,
                            const int4* __restrict__ IP4, const float* __restrict__ NRM,
                            const float* __restrict__ CB, __half* __restrict__ W16,
                            float4* __restrict__ zo)
{
    const int b = blockIdx.x;

    if (b < 8192) {                       // --- P conversion
        const int n4 = NF * NF / 4;
        int i = b * 1024 + threadIdx.x;
        #pragma unroll
        for (int j = 0; j < 4; ++j) {
            int k = i + j * 256;
            float4 v = (k < n4) ? Pi[k] : Pi2[k - n4];
            P16[2 * k]     = __floats2half2_rn(v.x, v.y);
            P16[2 * k + 1] = __floats2half2_rn(v.z, v.w);
        }
    } else if (b < 8704) {                // --- x conversion
        int i = (b - 8192) * 1024 + threadIdx.x;
        #pragma unroll
        for (int j = 0; j < 4; ++j) {
            int k = i + j * 256;
            float4 v = x[k];
            x16[2 * k]     = __floats2half2_rn(v.x, v.y);
            x16[2 * k + 1] = __floats2half2_rn(v.z, v.w);
        }
    } else if (b < 12800) {               // --- dequant pass 2
        __shared__ float cb[16];
        if (threadIdx.x < 16) cb[threadIdx.x] = CB[threadIdx.x];
        __syncthreads();
        int base = (b - 8704) * 512 + threadIdx.x;
        #pragma unroll
        for (int u = 0; u < 2; ++u) {
            int i = base + u * 256;
            int m  = i >> 9;
            int c4 = i & 511;
            int4 p = IP4[i];
            float s = __ldg(&NRM[(m << 5) + (c4 >> 4)]) * 0.08838834764831843f;
            __half2 h[4];
            h[0] = __floats2half2_rn(cb[p.x & 15] * s, cb[(p.x >> 4) & 15] * s);
            h[1] = __floats2half2_rn(cb[p.y & 15] * s, cb[(p.y >> 4) & 15] * s);
            h[2] = __floats2half2_rn(cb[p.z & 15] * s, cb[(p.z >> 4) & 15] * s);
            h[3] = __floats2half2_rn(cb[p.w & 15] * s, cb[(p.w >> 4) & 15] * s);
            *reinterpret_cast<uint4*>(W16 + (size_t)m * (2 * NF) + NF + c4 * 8) =
                *reinterpret_cast<uint4*>(h);
        }
    } else {                              // --- zero out
        int i = (b - 12800) * 1024 + threadIdx.x;
        #pragma unroll
        for (int j = 0; j < 4; ++j)
            zo[i + j * 256] = make_float4(0.f, 0.f, 0.f, 0.f);
    }
}

// ============================================================================
// GEMM1 4-warp + aux (r16 exact, measured): 128 threads, warp grid 2x2,
//   warp tile 64x64, 3-stage cp.async, fragment double-buffered, fp16 store.
//   Aux CTAs (blockIdx.y >= jTiles): dequant pass 1 (64 MB, MLP 6, guarded).
// ============================================================================
__global__ void __launch_bounds__(128, 2)
tq_hgemm1_w4(const __half* __restrict__ X, int ldx,
             const __half* __restrict__ W, int ldw,
             int ksteps, int jTiles, __half* __restrict__ Ch, int ldc,
             const int4* __restrict__ dq_i1, const float* __restrict__ dq_n1,
             const float* __restrict__ dq_c1, __half* __restrict__ dq_out)
{
    extern __shared__ __align__(1024) char dsm[];

    // ---------------- aux path: dq1 -----------------------------------------
    if ((int)blockIdx.y >= jTiles) {
        float* cb = reinterpret_cast<float*>(dsm);
        if (threadIdx.x < 16) cb[threadIdx.x] = dq_c1[threadIdx.x];
        __syncthreads();
        const int auxId  = (blockIdx.y - jTiles) * gridDim.x + blockIdx.x;
        const int nAux   = AUX_Y * gridDim.x;        // 40
        const int total   = NF * (NF / 2) / 4;       // 2M int4
        const int start6  = (auxId * 128 + threadIdx.x) * 6;
        const int stride6 = nAux * 128 * 6;
        for (int i0 = start6; i0 < total; i0 += stride6) {
            int4 p[6];
            #pragma unroll
            for (int u = 0; u < 6; ++u)
                p[u] = (i0 + u < total) ? dq_i1[i0 + u] : make_int4(0, 0, 0, 0);
            #pragma unroll
            for (int u = 0; u < 6; ++u) {
                int i = i0 + u;
                if (i >= total) break;
                int m  = i >> 9;
                int c4 = i & 511;
                float s = __ldg(&dq_n1[(m << 5) + (c4 >> 4)]) * 0.08838834764831843f;
                __half2 h[4];
                h[0] = __floats2half2_rn(cb[p[u].x & 15] * s, cb[(p[u].x >> 4) & 15] * s);
                h[1] = __floats2half2_rn(cb[p[u].y & 15] * s, cb[(p[u].y >> 4) & 15] * s);
                h[2] = __floats2half2_rn(cb[p[u].z & 15] * s, cb[(p[u].z >> 4) & 15] * s);
                h[3] = __floats2half2_rn(cb[p[u].w & 15] * s, cb[(p[u].w >> 4) & 15] * s);
                *reinterpret_cast<uint4*>(dq_out + (size_t)m * (2 * NF) + c4 * 8) =
                    *reinterpret_cast<uint4*>(h);
            }
        }
        return;
    }

    // ---------------- GEMM path ----------------------------------------------
    const uint32_t smBase = smem_u32(dsm);
    const int tid = threadIdx.x;
    const int wid = tid >> 5;
    const int lid = tid & 31;
    const int wm  = wid >> 1;
    const int wn  = wid & 1;
    const int tBase = blockIdx.x * TT;
    const int jBase = blockIdx.y * TJ;

    const __half* xb = X + (size_t)tBase * ldx;
    const __half* wb = W + (size_t)jBase * ldw;

    auto load_stage = [&](int slot, int step) {
        const int k0 = step * KSTEP;
        #pragma unroll
        for (int s = 0; s < 16; ++s) {
            int q = tid + s * 128;
            int r = q >> 3;
            int c = q & 7;
            const __half* src = (r < TT ? xb + (size_t)r * ldx
                                        : wb + (size_t)(r - TT) * ldw) + k0 + c * 8;
            uint32_t dst = smBase + slot * STAGE_BYTES + r * 128 + ((c ^ (r & 7)) * 16);
            asm volatile("cp.async.cg.shared.global [%0], [%1], 16;"
                         :: "r"(dst), "l"(src));
        }
    };

    const int swz  = lid & 7;
    const int rowA = wm * 64 + (lid & 7) + ((lid >> 3) & 1) * 8;
    const int pA   = lid >> 4;
    const int rowB = TT + wn * 64 + (lid & 7) + ((lid >> 4) & 1) * 8;
    const int pB   = (lid >> 3) & 1;

    float acc[4][8][4];
    #pragma unroll
    for (int ia = 0; ia < 4; ++ia)
        #pragma unroll
        for (int ib = 0; ib < 8; ++ib)
            #pragma unroll
            for (int ic = 0; ic < 4; ++ic) acc[ia][ib][ic] = 0.f;

    load_stage(0, 0);
    asm volatile("cp.async.commit_group;" ::: "memory");
    load_stage(1, 1);
    asm volatile("cp.async.commit_group;" ::: "memory");

    uint32_t a[2][4][4];
    uint32_t b[2][8][2];

    auto ldfrag = [&](int buf, uint32_t sb, int kb) {
        #pragma unroll
        for (int mi = 0; mi < 4; ++mi) {
            uint32_t ad = sb + (uint32_t)(rowA + mi * 16) * 128
                        + (uint32_t)(((kb * 2 + pA) ^ swz) * 16);
            TQ_LDSM4(a[buf][mi][0], a[buf][mi][1], a[buf][mi][2], a[buf][mi][3], ad);
        }
        #pragma unroll
        for (int gi = 0; gi < 4; ++gi) {
            uint32_t bd = sb + (uint32_t)(rowB + gi * 16) * 128
                        + (uint32_t)(((kb * 2 + pB) ^ swz) * 16);
            TQ_LDSM4(b[buf][2 * gi][0], b[buf][2 * gi][1],
                     b[buf][2 * gi + 1][0], b[buf][2 * gi + 1][1], bd);
        }
    };

    auto domma = [&](int buf) {
        #pragma unroll
        for (int mi = 0; mi < 4; ++mi)
            #pragma unroll
            for (int ni = 0; ni < 8; ++ni) {
                asm volatile(
                    "mma.sync.aligned.m16n8k16.row.col.f32.f16.f16.f32 "
                    "{%0,%1,%2,%3}, {%4,%5,%6,%7}, {%8,%9}, {%0,%1,%2,%3};"
                    : "+f"(acc[mi][ni][0]), "+f"(acc[mi][ni][1]),
                      "+f"(acc[mi][ni][2]), "+f"(acc[mi][ni][3])
                    : "r"(a[buf][mi][0]), "r"(a[buf][mi][1]),
                      "r"(a[buf][mi][2]), "r"(a[buf][mi][3]),
                      "r"(b[buf][ni][0]), "r"(b[buf][ni][1]));
            }
    };

    int slot = 0, pfslot = 2;
    for (int it = 0; it < ksteps; ++it) {
        asm volatile("cp.async.wait_group 1;" ::: "memory");
        __syncthreads();

        const int pf = it + NSTG - 1;
        if (pf < ksteps) load_stage(pfslot, pf);
        asm volatile("cp.async.commit_group;" ::: "memory");

        const uint32_t sb = smBase + slot * STAGE_BYTES;
        if (++slot == NSTG) slot = 0;
        if (++pfslot == NSTG) pfslot = 0;

        ldfrag(0, sb, 0);
        #pragma unroll
        for (int kb = 0; kb < 4; ++kb) {
            const int cur = kb & 1;
            if (kb < 3) ldfrag(cur ^ 1, sb, kb + 1);
            domma(cur);
        }
    }

    const int g  = lid >> 2;
    const int tg = lid & 3;
    #pragma unroll
    for (int mi = 0; mi < 4; ++mi) {
        #pragma unroll
        for (int ni = 0; ni < 8; ++ni) {
            int row = tBase + wm * 64 + mi * 16 + g;
            int col = jBase + wn * 64 + ni * 8 + tg * 2;
            __half2 h0 = __floats2half2_rn(acc[mi][ni][0], acc[mi][ni][1]);
            __half2 h1 = __floats2half2_rn(acc[mi][ni][2], acc[mi][ni][3]);
            *reinterpret_cast<__half2*>(Ch + (size_t)row * ldc + col)       = h0;
            *reinterpret_cast<__half2*>(Ch + (size_t)(row + 8) * ldc + col) = h1;
        }
    }
}

// ============================================================================
// GEMM2 4-warp (r15/r16 exact, measured 92.4 us): split-K 2, atomicAdd.
// ============================================================================
__global__ void __launch_bounds__(128, 2)
tq_hgemm2_w4(const __half* __restrict__ X, int ldx,
             const __half* __restrict__ W, int ldw,
             int ksteps, float* __restrict__ Cf, int ldc)
{
    extern __shared__ __align__(1024) char dsm[];
    const uint32_t smBase = smem_u32(dsm);

    const int tid = threadIdx.x;
    const int wid = tid >> 5;
    const int lid = tid & 31;
    const int wm  = wid >> 1;
    const int wn  = wid & 1;
    const int tBase = blockIdx.x * TT;
    const int jBase = blockIdx.y * TJ;
    const int kOff  = blockIdx.z * (ksteps * KSTEP);

    const __half* xb = X + (size_t)tBase * ldx + kOff;
    const __half* wb = W + (size_t)jBase * ldw + kOff;

    auto load_stage = [&](int slot, int step) {
        const int k0 = step * KSTEP;
        #pragma unroll
        for (int s = 0; s < 16; ++s) {
            int q = tid + s * 128;
            int r = q >> 3;
            int c = q & 7;
            const __half* src = (r < TT ? xb + (size_t)r * ldx
                                        : wb + (size_t)(r - TT) * ldw) + k0 + c * 8;
            uint32_t dst = smBase + slot * STAGE_BYTES + r * 128 + ((c ^ (r & 7)) * 16);
            asm volatile("cp.async.cg.shared.global [%0], [%1], 16;"
                         :: "r"(dst), "l"(src));
        }
    };

    const int swz  = lid & 7;
    const int rowA = wm * 64 + (lid & 7) + ((lid >> 3) & 1) * 8;
    const int pA   = lid >> 4;
    const int rowB = TT + wn * 64 + (lid & 7) + ((lid >> 4) & 1) * 8;
    const int pB   = (lid >> 3) & 1;

    float acc[4][8][4];
    #pragma unroll
    for (int ia = 0; ia < 4; ++ia)
        #pragma unroll
        for (int ib = 0; ib < 8; ++ib)
            #pragma unroll
            for (int ic = 0; ic < 4; ++ic) acc[ia][ib][ic] = 0.f;

    load_stage(0, 0);
    asm volatile("cp.async.commit_group;" ::: "memory");
    load_stage(1, 1);
    asm volatile("cp.async.commit_group;" ::: "memory");

    uint32_t a[2][4][4];
    uint32_t b[2][8][2];

    auto ldfrag = [&](int buf, uint32_t sb, int kb) {
        #pragma unroll
        for (int mi = 0; mi < 4; ++mi) {
            uint32_t ad = sb + (uint32_t)(rowA + mi * 16) * 128
                        + (uint32_t)(((kb * 2 + pA) ^ swz) * 16);
            TQ_LDSM4(a[buf][mi][0], a[buf][mi][1], a[buf][mi][2], a[buf][mi][3], ad);
        }
        #pragma unroll
        for (int gi = 0; gi < 4; ++gi) {
            uint32_t bd = sb + (uint32_t)(rowB + gi * 16) * 128
                        + (uint32_t)(((kb * 2 + pB) ^ swz) * 16);
            TQ_LDSM4(b[buf][2 * gi][0], b[buf][2 * gi][1],
                     b[buf][2 * gi + 1][0], b[buf][2 * gi + 1][1], bd);
        }
    };

    auto domma = [&](int buf) {
        #pragma unroll
        for (int mi = 0; mi < 4; ++mi)
            #pragma unroll
            for (int ni = 0; ni < 8; ++ni) {
                asm volatile(
                    "mma.sync.aligned.m16n8k16.row.col.f32.f16.f16.f32 "
                    "{%0,%1,%2,%3}, {%4,%5,%6,%7}, {%8,%9}, {%0,%1,%2,%3};"
                    : "+f"(acc[mi][ni][0]), "+f"(acc[mi][ni][1]),
                      "+f"(acc[mi][ni][2]), "+f"(acc[mi][ni][3])
                    : "r"(a[buf][mi][0]), "r"(a[buf][mi][1]),
                      "r"(a[buf][mi][2]), "r"(a[buf][mi][3]),
                      "r"(b[buf][ni][0]), "r"(b[buf][ni][1]));
            }
    };

    int slot = 0, pfslot = 2;
    for (int it = 0; it < ksteps; ++it) {
        asm volatile("cp.async.wait_group 1;" ::: "memory");
        __syncthreads();

        const int pf = it + NSTG - 1;
        if (pf < ksteps) load_stage(pfslot, pf);
        asm volatile("cp.async.commit_group;" ::: "memory");

        const uint32_t sb = smBase + slot * STAGE_BYTES;
        if (++slot == NSTG) slot = 0;
        if (++pfslot == NSTG) pfslot = 0;

        ldfrag(0, sb, 0);
        #pragma unroll
        for (int kb = 0; kb < 4; ++kb) {
            const int cur = kb & 1;
            if (kb < 3) ldfrag(cur ^ 1, sb, kb + 1);
            domma(cur);
        }
    }

    const int g  = lid >> 2;
    const int tg = lid & 3;
    #pragma unroll
    for (int mi = 0; mi < 4; ++mi) {
        #pragma unroll
        for (int ni = 0; ni < 8; ++ni) {
            int row = tBase + wm * 64 + mi * 16 + g;
            int col = jBase + wn * 64 + ni * 8 + tg * 2;
            atomicAdd(Cf + (size_t)row * ldc + col,           acc[mi][ni][0]);
            atomicAdd(Cf + (size_t)row * ldc + col + 1,       acc[mi][ni][1]);
            atomicAdd(Cf + (size_t)(row + 8) * ldc + col,     acc[mi][ni][2]);
            atomicAdd(Cf + (size_t)(row + 8) * ldc + col + 1, acc[mi][ni][3]);
        }
    }
}

// ============================================================================
// Launch: prep_all, GEMM1-w4+aux, GEMM2-w4  (3 launches)
// ============================================================================
extern "C" void kernel_launch(void* const* d_in, const int* in_sizes, int n_in,
                              void* d_out, int out_size) {
    (void)in_sizes; (void)n_in; (void)out_size;
    const float* x    = (const float*)d_in[0];
    const float* Pi   = (const float*)d_in[1];
    const int*   idx1 = (const int*)  d_in[2];
    const float* nrm1 = (const float*)d_in[3];
    const float* cb1  = (const float*)d_in[4];
    const int*   idx2 = (const int*)  d_in[5];
    const float* nrm2 = (const float*)d_in[6];
    const float* cb2  = (const float*)d_in[7];
    const float* Pi2  = (const float*)d_in[8];
    float* out = (float*)d_out;

    __half *px16, *pP16, *pW16, *pxr;
    cudaGetSymbolAddress((void**)&px16, g_x16);
    cudaGetSymbolAddress((void**)&pP16, g_P16);
    cudaGetSymbolAddress((void**)&pW16, g_W16);
    cudaGetSymbolAddress((void**)&pxr,  g_xr);

    cudaFuncSetAttribute(tq_hgemm1_w4, cudaFuncAttributeMaxDynamicSharedMemorySize,
                         SMEM_BYTES);
    cudaFuncSetAttribute(tq_hgemm2_w4, cudaFuncAttributeMaxDynamicSharedMemorySize,
                         SMEM_BYTES);

    // launch 1: all prep (P f2h, x f2h, dq2, zero out) — measured 37.9 us
    tq_prep_all<<<PREP_BLOCKS, 256>>>(
        (const float4*)Pi, (const float4*)Pi2, (__half2*)pP16,
        (const float4*)x, (__half2*)px16,
        (const int4*)idx2, nrm2, cb2, pW16,
        (float4*)out);

    // launch 2: GEMM1-w4 (256 CTAs) + 40 aux CTAs (dq1)
    //   xr[512, 8192] = x16 @ Pcat^T  (K = 4096)
    {
        dim3 grid(TOK / TT, 2 * NF / TJ + AUX_Y, 1);   // (4, 74) = 296 CTAs
        tq_hgemm1_w4<<<grid, 128, SMEM_BYTES>>>(
            px16, NF, pP16, NF, NF / KSTEP, 2 * NF / TJ, pxr, 2 * NF,
            (const int4*)idx1, nrm1, cb1, pW16);
    }

    // launch 3: GEMM2-w4  out += xr @ Wcat^T  (K = 8192, split-K 2)
    {
        dim3 grid(TOK / TT, NF / TJ, 2);               // (4, 32, 2) = 256 CTAs
        tq_hgemm2_w4<<<grid, 128, SMEM_BYTES>>>(pxr, 2 * NF, pW16, 2 * NF,
                                                (2 * NF / KSTEP) / 2, out, NF);
    }
}